// round 13
// baseline (speedup 1.0000x reference)
#include <cuda_runtime.h>
#include <cuda_bf16.h>
#include <mma.h>
#include <math.h>
#include <stdint.h>

using namespace nvcuda;

#define N_ATOMS 20000
#define N_EDGES 320000
#define FDIM    64
#define LT2     79       // ceil(20000/256) row-tiles for k_lin
#define ETILES  2500     // N_EDGES / 128

typedef unsigned long long ull;
typedef __nv_bfloat16 bf16;

// ---------------- device scratch (static, no allocations) ----------------
__device__ float g_comps[N_ATOMS * 9 * FDIM];   // Y (lin-pre out), [n][c][g]
__device__ float g_msg  [N_ATOMS * 9 * FDIM];   // messages [n][c][g]; later dX
__device__ float g_cfn  [9 * FDIM * N_ATOMS];   // comps in [c][f][n]
__device__ float g_rfv  [N_EDGES * 192];        // edge radial feats [e][k][f]
__device__ bf16  g_w0h[64 * 32],   g_w0l[64 * 32];
__device__ bf16  g_w1h[128 * 64],  g_w1l[128 * 64];
__device__ bf16  g_w2h[192 * 128], g_w2l[192 * 128];   // rows permuted: r=cc*64+f <-> neuron 3f+cc
__device__ int   g_cnt [N_ATOMS];
__device__ int   g_off [N_ATOMS + 1];
__device__ int   g_cur [N_ATOMS];
__device__ int   g_slot[N_EDGES];

// ---------------- generic helpers ----------------
__device__ __forceinline__ ull pack2(float x, float y) {
    ull r; asm("mov.b64 %0, {%1,%2};" : "=l"(r) : "f"(x), "f"(y)); return r;
}
__device__ __forceinline__ void unpack2(ull v, float& x, float& y) {
    asm("mov.b64 {%0,%1}, %2;" : "=f"(x), "=f"(y) : "l"(v));
}
__device__ __forceinline__ ull fma2(ull a, ull b, ull c) {
    ull d; asm("fma.rn.f32x2 %0, %1, %2, %3;" : "=l"(d) : "l"(a), "l"(b), "l"(c)); return d;
}
__device__ __forceinline__ float siluf(float x) {
    return __fdividef(x, 1.0f + __expf(-x));
}
__device__ __forceinline__ float bfround(float v) {
    return __bfloat162float(__float2bfloat16(v));
}
// comps order: 0:i  1:a01 2:a02 3:a12  4:s00 5:s01 6:s02 7:s11 8:s12
__device__ __forceinline__ void recon(const float* c, float* T) {
    T[0] = c[0] + c[4];  T[1] = c[1] + c[5];  T[2] = c[2] + c[6];
    T[3] = c[5] - c[1];  T[4] = c[0] + c[7];  T[5] = c[3] + c[8];
    T[6] = c[6] - c[2];  T[7] = c[8] - c[3];  T[8] = c[0] - c[4] - c[7];
}
__device__ __forceinline__ void madd3(const float* A, const float* B, float* P) {
#pragma unroll
    for (int i = 0; i < 3; i++)
#pragma unroll
        for (int j = 0; j < 3; j++) {
            float s = P[i * 3 + j];
#pragma unroll
            for (int k = 0; k < 3; k++) s += A[i * 3 + k] * B[k * 3 + j];
            P[i * 3 + j] = s;
        }
}
__device__ __forceinline__ void decomp(const float* P, float* c) {
    float dm = (P[0] + P[4] + P[8]) * (1.0f / 3.0f);
    c[0] = dm;
    c[1] = 0.5f * (P[1] - P[3]);
    c[2] = 0.5f * (P[2] - P[6]);
    c[3] = 0.5f * (P[5] - P[7]);
    c[4] = P[0] - dm;
    c[5] = 0.5f * (P[1] + P[3]);
    c[6] = 0.5f * (P[2] + P[6]);
    c[7] = P[4] - dm;
    c[8] = 0.5f * (P[5] + P[7]);
}

// ============== K_wsplit: one-time bf16 hi/lo weight split ==============
__global__ void k_wsplit(const float* __restrict__ W0, const float* __restrict__ W1,
                         const float* __restrict__ W2) {
    int i = blockIdx.x * 256 + threadIdx.x;
    if (i < 2048) {
        float v = W0[i]; float h = bfround(v);
        g_w0h[i] = __float2bfloat16(v); g_w0l[i] = __float2bfloat16(v - h);
    } else if (i < 10240) {
        int j = i - 2048;
        float v = W1[j]; float h = bfround(v);
        g_w1h[j] = __float2bfloat16(v); g_w1l[j] = __float2bfloat16(v - h);
    } else if (i < 34816) {
        int j = i - 10240;
        int r = j >> 7, k = j & 127;
        int cc = r >> 6, f = r & 63;
        float v = W2[(3 * f + cc) * 128 + k]; float h = bfround(v);
        g_w2h[j] = __float2bfloat16(v); g_w2l[j] = __float2bfloat16(v - h);
    }
}

// ============================================================================
// K_mlp: full 3-layer MLP, one 128-edge tile per block, wmma bf16x3.
// smem (bytes):
//   0      W0h [64][40], 5120 W0l                    -> 10240
//   10240  W1h [128][72], 28672 W1l                  -> 47104
//   47104  ST  f32 [128][36] (18432)                 -> 65536
//   65536  scratch (57344):
//          RFh [128][40]@65536, RFl@75776, A1h [128][72]@86016, A1l@104448
//          (L2 phase) W2h [96][136]@65536, W2l@91648
//   122880 H1h [128][136], 157696 H1l               -> 192512
//   192512 sB0(64f) 192768 sB1(128f) 193280 sB2(192f) 194048 sC(128f) -> 194560
// ============================================================================
__global__ void __launch_bounds__(512) k_mlp(
    const float* __restrict__ rf, const float* __restrict__ dij,
    const float* __restrict__ b0, const float* __restrict__ b1,
    const float* __restrict__ b2) {
    extern __shared__ char smb[];
    bf16* W0h = (bf16*)(smb + 0);
    bf16* W0l = (bf16*)(smb + 5120);
    bf16* W1h = (bf16*)(smb + 10240);
    bf16* W1l = (bf16*)(smb + 28672);
    float* ST  = (float*)(smb + 47104);
    bf16* RFh = (bf16*)(smb + 65536);
    bf16* RFl = (bf16*)(smb + 75776);
    bf16* A1h = (bf16*)(smb + 86016);
    bf16* A1l = (bf16*)(smb + 104448);
    bf16* W2h = (bf16*)(smb + 65536);
    bf16* W2l = (bf16*)(smb + 91648);
    bf16* H1h = (bf16*)(smb + 122880);
    bf16* H1l = (bf16*)(smb + 157696);
    float* sB0 = (float*)(smb + 192512);
    float* sB1 = (float*)(smb + 192768);
    float* sB2 = (float*)(smb + 193280);
    float* sC  = (float*)(smb + 194048);
    int t = threadIdx.x, w = t >> 5;
    int mi = w >> 1, nh = w & 1;
    int E0 = blockIdx.x * 128;

    // ---- stage weights (bf16 copies) + biases + rf split + cutoff ----
    for (int i = t; i < 2048; i += 512) {
        int r = i >> 5, k = i & 31;
        W0h[r * 40 + k] = g_w0h[i];
        W0l[r * 40 + k] = g_w0l[i];
    }
    for (int i = t; i < 8192; i += 512) {
        int r = i >> 6, k = i & 63;
        W1h[r * 72 + k] = g_w1h[i];
        W1l[r * 72 + k] = g_w1l[i];
    }
    if (t < 64) sB0[t] = b0[t];
    if (t < 128) sB1[t] = b1[t];
    if (t < 192) { int cc = t >> 6, f = t & 63; sB2[t] = b2[3 * f + cc]; }
    for (int i = t; i < 4096; i += 512) {
        int e = i >> 5, k = i & 31;
        float v = rf[(E0 + e) * 32 + k];
        float h = bfround(v);
        RFh[e * 40 + k] = __float2bfloat16(v);
        RFl[e * 40 + k] = __float2bfloat16(v - h);
    }
    if (t < 128) {
        float d = dij[E0 + t];
        sC[t] = (d < 1.0f) ? (0.5f * (cospif(d) + 1.0f)) : 0.0f;
    }
    __syncthreads();

    // ---- L0: [128,64] = RF[128,32] @ W0^T ----
    {
        wmma::fragment<wmma::accumulator, 16, 16, 16, float> a0[2];
#pragma unroll
        for (int j = 0; j < 2; j++) wmma::fill_fragment(a0[j], 0.0f);
#pragma unroll 1
        for (int p = 0; p < 3; p++) {
            const bf16* Ab = (p == 2) ? RFl : RFh;
            const bf16* Bb = (p == 1) ? W0l : W0h;
#pragma unroll
            for (int k = 0; k < 2; k++) {
                wmma::fragment<wmma::matrix_a, 16, 16, 16, bf16, wmma::row_major> af;
                wmma::load_matrix_sync(af, Ab + (16 * mi) * 40 + 16 * k, 40);
#pragma unroll
                for (int j = 0; j < 2; j++) {
                    int n = 2 * j + nh;
                    wmma::fragment<wmma::matrix_b, 16, 16, 16, bf16, wmma::col_major> bfr;
                    wmma::load_matrix_sync(bfr, Bb + (16 * n) * 40 + 16 * k, 40);
                    wmma::mma_sync(a0[j], af, bfr, a0[j]);
                }
            }
        }
#pragma unroll 1
        for (int r = 0; r < 2; r++) {
            __syncthreads();
            wmma::store_matrix_sync(ST + (16 * mi) * 36 + nh * 16, a0[r], 36, wmma::mem_row_major);
            __syncthreads();
            for (int i = t; i < 4096; i += 512) {
                int e = i >> 5, c = i & 31;
                int col = 32 * r + c;
                float v = siluf(ST[e * 36 + c] + sB0[col]);
                float h = bfround(v);
                A1h[e * 72 + col] = __float2bfloat16(v);
                A1l[e * 72 + col] = __float2bfloat16(v - h);
            }
        }
    }
    __syncthreads();

    // ---- L1: [128,128] = h0[128,64] @ W1^T ----
    {
        wmma::fragment<wmma::accumulator, 16, 16, 16, float> a1[4];
#pragma unroll
        for (int j = 0; j < 4; j++) wmma::fill_fragment(a1[j], 0.0f);
#pragma unroll 1
        for (int p = 0; p < 3; p++) {
            const bf16* Ab = (p == 2) ? A1l : A1h;
            const bf16* Bb = (p == 1) ? W1l : W1h;
#pragma unroll
            for (int k = 0; k < 4; k++) {
                wmma::fragment<wmma::matrix_a, 16, 16, 16, bf16, wmma::row_major> af;
                wmma::load_matrix_sync(af, Ab + (16 * mi) * 72 + 16 * k, 72);
#pragma unroll
                for (int j = 0; j < 4; j++) {
                    int n = 2 * j + nh;
                    wmma::fragment<wmma::matrix_b, 16, 16, 16, bf16, wmma::col_major> bfr;
                    wmma::load_matrix_sync(bfr, Bb + (16 * n) * 72 + 16 * k, 72);
                    wmma::mma_sync(a1[j], af, bfr, a1[j]);
                }
            }
        }
#pragma unroll 1
        for (int r = 0; r < 4; r++) {
            __syncthreads();
            wmma::store_matrix_sync(ST + (16 * mi) * 36 + nh * 16, a1[r], 36, wmma::mem_row_major);
            __syncthreads();
            for (int i = t; i < 4096; i += 512) {
                int e = i >> 5, c = i & 31;
                int col = 32 * r + c;
                float v = siluf(ST[e * 36 + c] + sB1[col]);
                float h = bfround(v);
                H1h[e * 136 + col] = __float2bfloat16(v);
                H1l[e * 136 + col] = __float2bfloat16(v - h);
            }
        }
    }
    __syncthreads();   // H1 complete; RF/A1 now dead

    // ---- L2: [128,192] = h1[128,128] @ W2p^T, two 96-col halves ----
    wmma::fragment<wmma::accumulator, 16, 16, 16, float> a2[6];
#pragma unroll
    for (int j = 0; j < 6; j++) wmma::fill_fragment(a2[j], 0.0f);
#pragma unroll 1
    for (int h2 = 0; h2 < 2; h2++) {
        __syncthreads();    // prior half's mma/cvt done before restaging W2 region
        for (int i = t; i < 12288; i += 512) {
            int rr = i >> 7, k = i & 127;
            int gr = 96 * h2 + rr;
            W2h[rr * 136 + k] = g_w2h[gr * 128 + k];
            W2l[rr * 136 + k] = g_w2l[gr * 128 + k];
        }
        __syncthreads();
#pragma unroll 1
        for (int p = 0; p < 3; p++) {
            const bf16* Ab = (p == 2) ? H1l : H1h;
            const bf16* Bb = (p == 1) ? W2l : W2h;
#pragma unroll 1
            for (int k = 0; k < 8; k++) {
                wmma::fragment<wmma::matrix_a, 16, 16, 16, bf16, wmma::row_major> af;
                wmma::load_matrix_sync(af, Ab + (16 * mi) * 136 + 16 * k, 136);
#pragma unroll
                for (int j3 = 0; j3 < 3; j3++) {
                    int j = 3 * h2 + j3;
                    int tn = 2 * (j - 3 * h2) + nh;       // local tile 0..5
                    wmma::fragment<wmma::matrix_b, 16, 16, 16, bf16, wmma::col_major> bfr;
                    wmma::load_matrix_sync(bfr, Bb + (16 * tn) * 136 + 16 * k, 136);
                    wmma::mma_sync(a2[j], af, bfr, a2[j]);
                }
            }
        }
#pragma unroll 1
        for (int r = 0; r < 3; r++) {
            __syncthreads();
            wmma::store_matrix_sync(ST + (16 * mi) * 36 + nh * 16, a2[3 * h2 + r], 36,
                                    wmma::mem_row_major);
            __syncthreads();
            for (int i = t; i < 4096; i += 512) {
                int e = i >> 5, c = i & 31;
                int col = 96 * h2 + 32 * r + c;
                float v = siluf(ST[e * 36 + c] + sB2[col]) * sC[e];
                g_rfv[(size_t)(E0 + e) * 192 + col] = v;
            }
        }
    }
}

// ============== K_decomp ==============
__global__ void __launch_bounds__(256) k_decomp(const float* __restrict__ X) {
    extern __shared__ float sT[];        // 576*33
    int t = threadIdx.x;
    int n0 = blockIdx.x * 32;
#pragma unroll 1
    for (int p = 0; p < 8; p++) {
        int a = p * 4 + (t >> 6);
        int f = t & 63;
        int n = n0 + a;
        const float* x = X + n * 576 + f * 9;
        float xv[9]; float tn = 0.f;
#pragma unroll
        for (int j = 0; j < 9; j++) { xv[j] = x[j]; tn += xv[j] * xv[j]; }
        float inv = 1.f / (tn + 1.f);
#pragma unroll
        for (int j = 0; j < 9; j++) xv[j] *= inv;
        float c9[9]; decomp(xv, c9);
#pragma unroll
        for (int c = 0; c < 9; c++) sT[(c * 64 + f) * 33 + a] = c9[c];
    }
    __syncthreads();
    for (int i = t; i < 18432; i += 256) {
        int a = i & 31, cf = i >> 5;
        g_cfn[cf * 20000 + n0 + a] = sT[cf * 33 + a];
    }
}

// ============== K_lin ==============
__global__ void __launch_bounds__(256) k_lin(const float* __restrict__ Wt, int post) {
    extern __shared__ ull sml[];
    ull*   sW = sml;
    float* sA = (float*)(sml + 4096);
    int t = threadIdx.x;
    int c  = blockIdx.x / LT2;
    int tb = blockIdx.x % LT2;
    int m = (c == 0) ? 0 : (c < 4) ? 1 : 2;
    const float* W = Wt + (post ? 3 : 0) * 4096 + m * 4096;
    for (int i = t; i < 4096; i += 256) {
        int k = i >> 6, g = i & 63;
        float w = W[g * 64 + k];
        sW[i] = pack2(w, w);
    }
    int n0 = tb * 256;
    int rows = N_ATOMS - n0; if (rows > 256) rows = 256;
    for (int i = t; i < 16384; i += 256) {
        int f = i >> 8, nl = i & 255;
        sA[f * 264 + nl] = (nl < rows) ? g_cfn[(c * 64 + f) * 20000 + n0 + nl] : 0.f;
    }
    __syncthreads();
    int r0 = t >> 4;
    int c0 = t & 15;
    ull acc[4][8];
#pragma unroll
    for (int j = 0; j < 4; j++)
#pragma unroll
        for (int p = 0; p < 8; p++) acc[j][p] = 0;
#pragma unroll 2
    for (int k = 0; k < 64; k++) {
        const float* row = sA + k * 264;
        ulonglong2 hA = *(const ulonglong2*)&row[8 * r0];
        ulonglong2 hB = *(const ulonglong2*)&row[8 * r0 + 4];
        ulonglong2 hC = *(const ulonglong2*)&row[128 + 8 * r0];
        ulonglong2 hD = *(const ulonglong2*)&row[128 + 8 * r0 + 4];
        ulonglong2 wA = *(const ulonglong2*)(sW + k * 64 + 4 * c0);
        ulonglong2 wB = *(const ulonglong2*)(sW + k * 64 + 4 * c0 + 2);
        ull w0 = wA.x, w1 = wA.y, w2 = wB.x, w3 = wB.y;
        ull h[8] = {hA.x, hA.y, hB.x, hB.y, hC.x, hC.y, hD.x, hD.y};
#pragma unroll
        for (int p = 0; p < 8; p++) {
            acc[0][p] = fma2(w0, h[p], acc[0][p]);
            acc[1][p] = fma2(w1, h[p], acc[1][p]);
            acc[2][p] = fma2(w2, h[p], acc[2][p]);
            acc[3][p] = fma2(w3, h[p], acc[3][p]);
        }
    }
    __syncthreads();
    float* sO = sA;
#pragma unroll
    for (int j = 0; j < 4; j++) {
        int g = 4 * c0 + j;
#pragma unroll
        for (int p = 0; p < 8; p++) {
            int rb = (p < 4) ? (8 * r0 + 2 * p) : (128 + 8 * r0 + 2 * (p - 4));
            float x, y; unpack2(acc[j][p], x, y);
            sO[rb * 66 + g]       = x;
            sO[(rb + 1) * 66 + g] = y;
        }
    }
    __syncthreads();
    float* outp = post ? g_msg : g_comps;
    for (int i = t; i < 16384; i += 256) {
        int nl = i >> 6, g = i & 63;
        if (nl < rows) outp[(n0 + nl) * 576 + c * 64 + g] = sO[nl * 66 + g];
    }
}

// ============== CSR build ==============
__global__ void k_zero() {
    int i = blockIdx.x * blockDim.x + threadIdx.x;
    if (i < N_ATOMS) g_cnt[i] = 0;
}
__global__ void k_hist(const int* __restrict__ pr) {
    int e = blockIdx.x * blockDim.x + threadIdx.x;
    if (e < N_EDGES) atomicAdd(&g_cnt[pr[e]], 1);
}
__global__ void k_scan() {
    __shared__ int s[1024];
    const int CH = 20;
    int t = threadIdx.x;
    int base = t * CH;
    int local[CH];
    int sum = 0;
#pragma unroll
    for (int i = 0; i < CH; i++) {
        int idx = base + i;
        int v = (idx < N_ATOMS) ? g_cnt[idx] : 0;
        local[i] = sum; sum += v;
    }
    s[t] = sum; __syncthreads();
    for (int d = 1; d < 1024; d <<= 1) {
        int v = (t >= d) ? s[t - d] : 0;
        __syncthreads();
        s[t] += v;
        __syncthreads();
    }
    int pre = (t == 0) ? 0 : s[t - 1];
#pragma unroll
    for (int i = 0; i < CH; i++) {
        int idx = base + i;
        if (idx < N_ATOMS) { int o = pre + local[i]; g_off[idx] = o; g_cur[idx] = o; }
    }
    if (t == 1023) g_off[N_ATOMS] = s[1023];
}
__global__ void k_scatter(const int* __restrict__ pr) {
    int e = blockIdx.x * blockDim.x + threadIdx.x;
    if (e < N_EDGES) {
        int pos = atomicAdd(&g_cur[pr[e]], 1);
        g_slot[pos] = e;
    }
}

// ============== K_reduce ==============
__global__ void k_reduce(const int* __restrict__ pr) {
    int lane = threadIdx.x & 31;
    int wid = threadIdx.x >> 5;
    for (int n = blockIdx.x * (blockDim.x >> 5) + wid; n < N_ATOMS;
         n += gridDim.x * (blockDim.x >> 5)) {
        float2 acc[9];
#pragma unroll
        for (int c = 0; c < 9; c++) acc[c] = make_float2(0.f, 0.f);
        int beg = g_off[n], end = g_off[n + 1];
        for (int j = beg; j < end; j++) {
            int e = g_slot[j];
            int s = pr[N_EDGES + e];
            const float2* rp = (const float2*)(g_rfv + (size_t)e * 192);
            float2 r0 = rp[lane];
            float2 r1 = rp[32 + lane];
            float2 r2 = rp[64 + lane];
            const float2* cp = (const float2*)(g_comps + s * 576);
#pragma unroll
            for (int c = 0; c < 9; c++) {
                float2 v = cp[c * 32 + lane];
                float2 sc = (c == 0) ? r0 : (c < 4) ? r1 : r2;
                acc[c].x += sc.x * v.x;
                acc[c].y += sc.y * v.y;
            }
        }
        float2* mp = (float2*)(g_msg + n * 576);
#pragma unroll
        for (int c = 0; c < 9; c++) mp[c * 32 + lane] = acc[c];
    }
}

// ============== K_prod ==============
__global__ void __launch_bounds__(256) k_prod(const float* __restrict__ chg) {
    extern __shared__ float sT[];
    int t = threadIdx.x;
    int n0 = blockIdx.x * 32;
#pragma unroll 1
    for (int p = 0; p < 8; p++) {
        int a = p * 4 + (t >> 6);
        int g = t & 63;
        int n = n0 + a;
        float q = 1.0f + 0.1f * chg[n];
        float cm[9], cy[9];
#pragma unroll
        for (int c = 0; c < 9; c++) {
            cm[c] = g_msg[n * 576 + c * 64 + g];
            cy[c] = g_comps[n * 576 + c * 64 + g];
        }
        float M[9], Y[9];
        recon(cm, M); recon(cy, Y);
        float P[9];
#pragma unroll
        for (int j = 0; j < 9; j++) P[j] = 0.f;
        madd3(M, Y, P);
        madd3(Y, M, P);
        float tn2 = 0.f;
#pragma unroll
        for (int j = 0; j < 9; j++) { P[j] *= q; tn2 += P[j] * P[j]; }
        float invn = 1.f / (tn2 + 1.f);
        float c9[9]; decomp(P, c9);
#pragma unroll
        for (int c = 0; c < 9; c++) sT[(c * 64 + g) * 33 + a] = c9[c] * invn;
    }
    __syncthreads();
    for (int i = t; i < 18432; i += 256) {
        int a = i & 31, cf = i >> 5;
        g_cfn[cf * 20000 + n0 + a] = sT[cf * 33 + a];
    }
}

// ============== K_finish ==============
__global__ void __launch_bounds__(256) k_finish(const float* __restrict__ X,
                                                const float* __restrict__ chg,
                                                float* __restrict__ out) {
    int idx = blockIdx.x * 256 + threadIdx.x;
    if (idx >= N_ATOMS * 64) return;
    int n = idx >> 6, g = idx & 63;
    float q = 1.0f + 0.1f * chg[n];
    const float* x = X + n * 576 + g * 9;
    float xv[9]; float tn = 0.f;
#pragma unroll
    for (int j = 0; j < 9; j++) { xv[j] = x[j]; tn += xv[j] * xv[j]; }
    float inv = 1.f / (tn + 1.f);
#pragma unroll
    for (int j = 0; j < 9; j++) xv[j] *= inv;
    float cd[9];
#pragma unroll
    for (int c = 0; c < 9; c++) cd[c] = g_msg[n * 576 + c * 64 + g];
    float dx[9]; recon(cd, dx);
    float dd[9];
#pragma unroll
    for (int j = 0; j < 9; j++) dd[j] = 0.f;
    madd3(dx, dx, dd);
#pragma unroll
    for (int j = 0; j < 9; j++)
        out[n * 576 + g * 9 + j] = xv[j] + dx[j] + q * dd[j];
}

// ---------------- launch ----------------
extern "C" void kernel_launch(void* const* d_in, const int* in_sizes, int n_in,
                              void* d_out, int out_size) {
    const float* X   = (const float*)d_in[0];
    const int*   pr  = (const int*)d_in[1];
    const float* dij = (const float*)d_in[2];
    const float* rf  = (const float*)d_in[3];
    const float* chg = (const float*)d_in[4];
    const float* W0  = (const float*)d_in[5];
    const float* b0  = (const float*)d_in[6];
    const float* W1  = (const float*)d_in[7];
    const float* b1  = (const float*)d_in[8];
    const float* W2  = (const float*)d_in[9];
    const float* b2  = (const float*)d_in[10];
    const float* Wt  = (const float*)d_in[11];
    float* out = (float*)d_out;

    const int smem_mlp = 194560;
    const int smem_tr  = 576 * 33 * 4;                  // 76032
    const int smem_lin = 4096 * 8 + 16896 * 4;          // 100352
    cudaFuncSetAttribute(k_mlp, cudaFuncAttributeMaxDynamicSharedMemorySize, smem_mlp);
    cudaFuncSetAttribute(k_decomp, cudaFuncAttributeMaxDynamicSharedMemorySize, smem_tr);
    cudaFuncSetAttribute(k_prod,   cudaFuncAttributeMaxDynamicSharedMemorySize, smem_tr);
    cudaFuncSetAttribute(k_lin,    cudaFuncAttributeMaxDynamicSharedMemorySize, smem_lin);

    k_zero<<<(N_ATOMS + 255) / 256, 256>>>();
    k_hist<<<(N_EDGES + 255) / 256, 256>>>(pr);
    k_wsplit<<<(34816 + 255) / 256, 256>>>(W0, W1, W2);
    k_mlp<<<ETILES, 512, smem_mlp>>>(rf, dij, b0, b1, b2);   // slot 4: profiled
    k_scan<<<1, 1024>>>();
    k_scatter<<<(N_EDGES + 255) / 256, 256>>>(pr);
    k_decomp<<<625, 256, smem_tr>>>(X);
    k_lin<<<9 * LT2, 256, smem_lin>>>(Wt, 0);
    k_reduce<<<2500, 256>>>(pr);
    k_prod<<<625, 256, smem_tr>>>(chg);
    k_lin<<<9 * LT2, 256, smem_lin>>>(Wt, 1);
    k_finish<<<(N_ATOMS * 64 + 255) / 256, 256>>>(X, chg, out);
}

// round 15
// speedup vs baseline: 1.6334x; 1.6334x over previous
#include <cuda_runtime.h>
#include <math.h>

#define N_ATOMS 20000
#define N_EDGES 320000
#define FDIM    64
#define NTILES  2500     // N_EDGES / 128
#define LT2     79       // ceil(20000/256) row-tiles for k_lin

typedef unsigned long long ull;

// ---------------- device scratch (static, no allocations) ----------------
__device__ float g_comps[N_ATOMS * 9 * FDIM];   // Y (lin-pre out), [n][c][g]
__device__ float g_msg  [N_ATOMS * 9 * FDIM];   // messages [n][c][g]; later dX
__device__ float g_cfn  [9 * FDIM * N_ATOMS];   // comps in [c][f][n]
__device__ float g_rfv  [N_EDGES * 192];        // edge radial feats [e][k][f]
__device__ int   g_cnt [N_ATOMS];
__device__ int   g_off [N_ATOMS + 1];
__device__ int   g_cur [N_ATOMS];
__device__ int   g_slot[N_EDGES];

// ---------------- helpers ----------------
__device__ __forceinline__ ull pack2(float x, float y) {
    ull r; asm("mov.b64 %0, {%1,%2};" : "=l"(r) : "f"(x), "f"(y)); return r;
}
__device__ __forceinline__ void unpack2(ull v, float& x, float& y) {
    asm("mov.b64 {%0,%1}, %2;" : "=f"(x), "=f"(y) : "l"(v));
}
__device__ __forceinline__ ull fma2(ull a, ull b, ull c) {
    ull d; asm("fma.rn.f32x2 %0, %1, %2, %3;" : "=l"(d) : "l"(a), "l"(b), "l"(c)); return d;
}
__device__ __forceinline__ float siluf(float x) {
    return __fdividef(x, 1.0f + __expf(-x));
}
// comps order: 0:i  1:a01 2:a02 3:a12  4:s00 5:s01 6:s02 7:s11 8:s12
__device__ __forceinline__ void recon(const float* c, float* T) {
    T[0] = c[0] + c[4];  T[1] = c[1] + c[5];  T[2] = c[2] + c[6];
    T[3] = c[5] - c[1];  T[4] = c[0] + c[7];  T[5] = c[3] + c[8];
    T[6] = c[6] - c[2];  T[7] = c[8] - c[3];  T[8] = c[0] - c[4] - c[7];
}
__device__ __forceinline__ void madd3(const float* A, const float* B, float* P) {
#pragma unroll
    for (int i = 0; i < 3; i++)
#pragma unroll
        for (int j = 0; j < 3; j++) {
            float s = P[i * 3 + j];
#pragma unroll
            for (int k = 0; k < 3; k++) s += A[i * 3 + k] * B[k * 3 + j];
            P[i * 3 + j] = s;
        }
}
__device__ __forceinline__ void decomp(const float* P, float* c) {
    float dm = (P[0] + P[4] + P[8]) * (1.0f / 3.0f);
    c[0] = dm;
    c[1] = 0.5f * (P[1] - P[3]);
    c[2] = 0.5f * (P[2] - P[6]);
    c[3] = 0.5f * (P[5] - P[7]);
    c[4] = P[0] - dm;
    c[5] = 0.5f * (P[1] + P[3]);
    c[6] = 0.5f * (P[2] + P[6]);
    c[7] = P[4] - dm;
    c[8] = 0.5f * (P[5] + P[7]);
}

// ============== K_decomp: normalize X, decompose -> g_cfn [c][f][n] ==============
__global__ void __launch_bounds__(256) k_decomp(const float* __restrict__ X) {
    extern __shared__ float sT[];        // 576*33 = 19008 floats
    int t = threadIdx.x;
    int n0 = blockIdx.x * 32;
#pragma unroll 1
    for (int p = 0; p < 8; p++) {
        int a = p * 4 + (t >> 6);        // 0..31
        int f = t & 63;
        int n = n0 + a;
        const float* x = X + n * 576 + f * 9;
        float xv[9]; float tn = 0.f;
#pragma unroll
        for (int j = 0; j < 9; j++) { xv[j] = x[j]; tn += xv[j] * xv[j]; }
        float inv = 1.f / (tn + 1.f);
#pragma unroll
        for (int j = 0; j < 9; j++) xv[j] *= inv;
        float c9[9]; decomp(xv, c9);
#pragma unroll
        for (int c = 0; c < 9; c++) sT[(c * 64 + f) * 33 + a] = c9[c];
    }
    __syncthreads();
    for (int i = t; i < 18432; i += 256) {
        int a = i & 31, cf = i >> 5;
        g_cfn[cf * 20000 + n0 + a] = sT[cf * 33 + a];
    }
}

// ============== K_lin: per-c GEMM, 256-row tiles, (w,w)-dup weights ==============
__global__ void __launch_bounds__(256) k_lin(const float* __restrict__ Wt, int post) {
    extern __shared__ ull sml[];
    ull*   sW = sml;                     // 4096 : [k<64][g<64] (w,w)
    float* sA = (float*)(sml + 4096);    // 64*264 = 16896 floats
    int t = threadIdx.x;
    int c  = blockIdx.x / LT2;
    int tb = blockIdx.x % LT2;
    int m = (c == 0) ? 0 : (c < 4) ? 1 : 2;
    const float* W = Wt + (post ? 3 : 0) * 4096 + m * 4096;
    for (int i = t; i < 4096; i += 256) {
        int k = i >> 6, g = i & 63;
        float w = W[g * 64 + k];
        sW[i] = pack2(w, w);
    }
    int n0 = tb * 256;
    int rows = N_ATOMS - n0; if (rows > 256) rows = 256;
    for (int i = t; i < 16384; i += 256) {
        int f = i >> 8, nl = i & 255;
        sA[f * 264 + nl] = (nl < rows) ? g_cfn[(c * 64 + f) * 20000 + n0 + nl] : 0.f;
    }
    __syncthreads();
    int r0 = t >> 4;      // rows 8*r0.. (low tile) and 128+8*r0.. (high tile)
    int c0 = t & 15;      // g = 4*c0..
    ull acc[4][8];
#pragma unroll
    for (int j = 0; j < 4; j++)
#pragma unroll
        for (int p = 0; p < 8; p++) acc[j][p] = 0;
#pragma unroll 2
    for (int k = 0; k < 64; k++) {
        const float* row = sA + k * 264;
        ulonglong2 hA = *(const ulonglong2*)&row[8 * r0];
        ulonglong2 hB = *(const ulonglong2*)&row[8 * r0 + 4];
        ulonglong2 hC = *(const ulonglong2*)&row[128 + 8 * r0];
        ulonglong2 hD = *(const ulonglong2*)&row[128 + 8 * r0 + 4];
        ulonglong2 wA = *(const ulonglong2*)(sW + k * 64 + 4 * c0);
        ulonglong2 wB = *(const ulonglong2*)(sW + k * 64 + 4 * c0 + 2);
        ull w0 = wA.x, w1 = wA.y, w2 = wB.x, w3 = wB.y;
        ull h[8] = {hA.x, hA.y, hB.x, hB.y, hC.x, hC.y, hD.x, hD.y};
#pragma unroll
        for (int p = 0; p < 8; p++) {
            acc[0][p] = fma2(w0, h[p], acc[0][p]);
            acc[1][p] = fma2(w1, h[p], acc[1][p]);
            acc[2][p] = fma2(w2, h[p], acc[2][p]);
            acc[3][p] = fma2(w3, h[p], acc[3][p]);
        }
    }
    __syncthreads();
    float* sO = sA;                      // [nl<256][66]
#pragma unroll
    for (int j = 0; j < 4; j++) {
        int g = 4 * c0 + j;
#pragma unroll
        for (int p = 0; p < 8; p++) {
            int rb = (p < 4) ? (8 * r0 + 2 * p) : (128 + 8 * r0 + 2 * (p - 4));
            float x, y; unpack2(acc[j][p], x, y);
            sO[rb * 66 + g]       = x;
            sO[(rb + 1) * 66 + g] = y;
        }
    }
    __syncthreads();
    float* outp = post ? g_msg : g_comps;
    for (int i = t; i < 16384; i += 256) {
        int nl = i >> 6, g = i & 63;
        if (nl < rows) outp[(n0 + nl) * 576 + c * 64 + g] = sO[nl * 66 + g];
    }
}

// ============== CSR build ==============
__global__ void k_zero() {
    int i = blockIdx.x * blockDim.x + threadIdx.x;
    if (i < N_ATOMS) g_cnt[i] = 0;
}
__global__ void k_hist(const int* __restrict__ pr) {
    int e = blockIdx.x * blockDim.x + threadIdx.x;
    if (e < N_EDGES) atomicAdd(&g_cnt[pr[e]], 1);   // dst = row 0
}
__global__ void k_scan() {                          // 1 block, 1024 threads
    __shared__ int s[1024];
    const int CH = 20;
    int t = threadIdx.x;
    int base = t * CH;
    int local[CH];
    int sum = 0;
#pragma unroll
    for (int i = 0; i < CH; i++) {
        int idx = base + i;
        int v = (idx < N_ATOMS) ? g_cnt[idx] : 0;
        local[i] = sum; sum += v;
    }
    s[t] = sum; __syncthreads();
    for (int d = 1; d < 1024; d <<= 1) {
        int v = (t >= d) ? s[t - d] : 0;
        __syncthreads();
        s[t] += v;
        __syncthreads();
    }
    int pre = (t == 0) ? 0 : s[t - 1];
#pragma unroll
    for (int i = 0; i < CH; i++) {
        int idx = base + i;
        if (idx < N_ATOMS) { int o = pre + local[i]; g_off[idx] = o; g_cur[idx] = o; }
    }
    if (t == 1023) g_off[N_ATOMS] = s[1023];
}
__global__ void k_scatter(const int* __restrict__ pr) {
    int e = blockIdx.x * blockDim.x + threadIdx.x;
    if (e < N_EDGES) {
        int pos = atomicAdd(&g_cur[pr[e]], 1);
        g_slot[pos] = e;
    }
}

// ============== K2: edge MLP — register-tiled, 256 threads, 8-edge x 4-pair tiles ==============
// Crossbar-balanced: bytes per fma2 halved vs the 4-edge tile.
#define HS 132
__global__ void __launch_bounds__(256)
k_edge_mlp(const float* __restrict__ rf, const float* __restrict__ dij,
           const float* __restrict__ W0, const float* __restrict__ b0,
           const float* __restrict__ W1, const float* __restrict__ b1,
           const float* __restrict__ W2, const float* __restrict__ b2) {
    extern __shared__ ull smu[];
    ull* sW0 = smu;                  // 1024  : [k<32][p<32]
    ull* sW1 = sW0 + 1024;           // 4096  : [k<64][p<64]
    ull* sW2 = sW1 + 4096;           // 12288 : [k<128][j<96], j = c*32+p
    ull* sB0 = sW2 + 12288;          // 32
    ull* sB1 = sB0 + 32;             // 64
    ull* sB2 = sB1 + 64;             // 96
    float* sRF = (float*)(sB2 + 96); // 4224  : [e<128][33]
    float* sH0 = sRF + 4224;         // 64*HS = 8448
    float* sH1 = sH0 + 64 * HS;      // 8448
    float* sC  = sH1 + 64 * HS;      // 128
    int t = threadIdx.x;

    for (int i = t; i < 1024; i += 256) {
        int k = i >> 5, p = i & 31;
        sW0[i] = pack2(W0[(2 * p) * 32 + k], W0[(2 * p + 1) * 32 + k]);
    }
    for (int i = t; i < 4096; i += 256) {
        int k = i >> 6, p = i & 63;
        sW1[i] = pack2(W1[(2 * p) * 64 + k], W1[(2 * p + 1) * 64 + k]);
    }
    for (int i = t; i < 12288; i += 256) {
        int k = i / 96, j = i % 96, c = j >> 5, p = j & 31;
        // output neuron o = 3f + c ; pair p covers f=2p, 2p+1
        sW2[i] = pack2(W2[(6 * p + c) * 128 + k], W2[(6 * p + 3 + c) * 128 + k]);
    }
    if (t < 32) sB0[t] = pack2(b0[2 * t], b0[2 * t + 1]);
    else if (t >= 64 && t < 128) { int u = t - 64; sB1[u] = pack2(b1[2 * u], b1[2 * u + 1]); }
    else if (t >= 128 && t < 224) {
        int u = t - 128; int c = u >> 5, p = u & 31;
        sB2[u] = pack2(b2[6 * p + c], b2[6 * p + 3 + c]);
    }
    __syncthreads();

    int r0 = t >> 4;     // 0..15 : edges 8*r0..8*r0+7
    int c0 = t & 15;     // 0..15

    for (int tile = blockIdx.x; tile < NTILES; tile += gridDim.x) {
        int E0 = tile * 128;
#pragma unroll
        for (int q = 0; q < 4; q++) {
            int lin = t + q * 256;
            float4 v = ((const float4*)(rf + E0 * 32))[lin];
            int e = lin >> 3, kq = lin & 7;
            sRF[e * 33 + 4 * kq + 0] = v.x;
            sRF[e * 33 + 4 * kq + 1] = v.y;
            sRF[e * 33 + 4 * kq + 2] = v.z;
            sRF[e * 33 + 4 * kq + 3] = v.w;
        }
        if (t < 128) {
            float d = dij[E0 + t];
            sC[t] = (d < 1.0f) ? (0.5f * (cospif(d) + 1.0f)) : 0.0f;
        }
        __syncthreads();

        // ---- L0: 32 -> 64 (pairs 2*c0, 2*c0+1; 8 edges) ----
        {
            ull a0[2][8];
#pragma unroll
            for (int j = 0; j < 2; j++)
#pragma unroll
                for (int i = 0; i < 8; i++) a0[j][i] = sB0[2 * c0 + j];
#pragma unroll 4
            for (int k = 0; k < 32; k++) {
                ulonglong2 wv = *(const ulonglong2*)(sW0 + k * 32 + 2 * c0);
                ull w0v = wv.x, w1v = wv.y;
#pragma unroll
                for (int i = 0; i < 8; i++) {
                    float h = sRF[(8 * r0 + i) * 33 + k];
                    ull hb = pack2(h, h);
                    a0[0][i] = fma2(w0v, hb, a0[0][i]);
                    a0[1][i] = fma2(w1v, hb, a0[1][i]);
                }
            }
#pragma unroll
            for (int j = 0; j < 2; j++) {
                float lo[8], hi[8];
#pragma unroll
                for (int i = 0; i < 8; i++) {
                    float x, y; unpack2(a0[j][i], x, y);
                    lo[i] = siluf(x); hi[i] = siluf(y);
                }
                int kn = (2 * c0 + j) * 2;
                *(float4*)&sH0[kn * HS + 8 * r0]           = make_float4(lo[0], lo[1], lo[2], lo[3]);
                *(float4*)&sH0[kn * HS + 8 * r0 + 4]       = make_float4(lo[4], lo[5], lo[6], lo[7]);
                *(float4*)&sH0[(kn + 1) * HS + 8 * r0]     = make_float4(hi[0], hi[1], hi[2], hi[3]);
                *(float4*)&sH0[(kn + 1) * HS + 8 * r0 + 4] = make_float4(hi[4], hi[5], hi[6], hi[7]);
            }
        }
        __syncthreads();

        // ---- L1: 64 -> 128 (pairs 4*c0..4*c0+3; 8 edges) ----
        {
            ull a1[4][8];
#pragma unroll
            for (int j = 0; j < 4; j++)
#pragma unroll
                for (int i = 0; i < 8; i++) a1[j][i] = sB1[4 * c0 + j];
#pragma unroll 2
            for (int k = 0; k < 64; k++) {
                float4 hA = *(const float4*)&sH0[k * HS + 8 * r0];
                float4 hB = *(const float4*)&sH0[k * HS + 8 * r0 + 4];
                ulonglong2 wA = *(const ulonglong2*)(sW1 + k * 64 + 4 * c0);
                ulonglong2 wB = *(const ulonglong2*)(sW1 + k * 64 + 4 * c0 + 2);
                ull w0v = wA.x, w1v = wA.y, w2v = wB.x, w3v = wB.y;
                float h[8] = {hA.x, hA.y, hA.z, hA.w, hB.x, hB.y, hB.z, hB.w};
#pragma unroll
                for (int i = 0; i < 8; i++) {
                    ull hb = pack2(h[i], h[i]);
                    a1[0][i] = fma2(w0v, hb, a1[0][i]);
                    a1[1][i] = fma2(w1v, hb, a1[1][i]);
                    a1[2][i] = fma2(w2v, hb, a1[2][i]);
                    a1[3][i] = fma2(w3v, hb, a1[3][i]);
                }
            }
            __syncthreads();   // all L1 reads of sH0 done before overwrite
#pragma unroll
            for (int j = 0; j < 4; j++) {
                int p = 4 * c0 + j;          // 0..63
                float lo[8], hi[8];
#pragma unroll
                for (int i = 0; i < 8; i++) {
                    float x, y; unpack2(a1[j][i], x, y);
                    lo[i] = siluf(x); hi[i] = siluf(y);
                }
                float* dst = (p < 32) ? sH1 : sH0;
                int kn = (p < 32) ? (2 * p) : (2 * p - 64);
                *(float4*)&dst[kn * HS + 8 * r0]           = make_float4(lo[0], lo[1], lo[2], lo[3]);
                *(float4*)&dst[kn * HS + 8 * r0 + 4]       = make_float4(lo[4], lo[5], lo[6], lo[7]);
                *(float4*)&dst[(kn + 1) * HS + 8 * r0]     = make_float4(hi[0], hi[1], hi[2], hi[3]);
                *(float4*)&dst[(kn + 1) * HS + 8 * r0 + 4] = make_float4(hi[4], hi[5], hi[6], hi[7]);
            }
        }
        __syncthreads();

        // ---- L2: 128 -> 192 (pairs 6*c0..6*c0+5; 8 edges) ----
        ull a2[6][8];
#pragma unroll
        for (int jj = 0; jj < 6; jj++)
#pragma unroll
            for (int i = 0; i < 8; i++) a2[jj][i] = sB2[6 * c0 + jj];
        // phase 0: k 0..63 from sH1
#pragma unroll 2
        for (int kl = 0; kl < 64; kl++) {
            float4 hA = *(const float4*)&sH1[kl * HS + 8 * r0];
            float4 hB = *(const float4*)&sH1[kl * HS + 8 * r0 + 4];
            const ull* wrow = sW2 + kl * 96 + 6 * c0;
            ulonglong2 wv0 = *(const ulonglong2*)(wrow);
            ulonglong2 wv1 = *(const ulonglong2*)(wrow + 2);
            ulonglong2 wv2 = *(const ulonglong2*)(wrow + 4);
            ull wp0 = wv0.x, wp1 = wv0.y, wp2 = wv1.x, wp3 = wv1.y, wp4 = wv2.x, wp5 = wv2.y;
            float h[8] = {hA.x, hA.y, hA.z, hA.w, hB.x, hB.y, hB.z, hB.w};
#pragma unroll
            for (int i = 0; i < 8; i++) {
                ull hb = pack2(h[i], h[i]);
                a2[0][i] = fma2(wp0, hb, a2[0][i]);
                a2[1][i] = fma2(wp1, hb, a2[1][i]);
                a2[2][i] = fma2(wp2, hb, a2[2][i]);
                a2[3][i] = fma2(wp3, hb, a2[3][i]);
                a2[4][i] = fma2(wp4, hb, a2[4][i]);
                a2[5][i] = fma2(wp5, hb, a2[5][i]);
            }
        }
        // phase 1: k 64..127 from sH0
#pragma unroll 2
        for (int kl = 0; kl < 64; kl++) {
            float4 hA = *(const float4*)&sH0[kl * HS + 8 * r0];
            float4 hB = *(const float4*)&sH0[kl * HS + 8 * r0 + 4];
            const ull* wrow = sW2 + (64 + kl) * 96 + 6 * c0;
            ulonglong2 wv0 = *(const ulonglong2*)(wrow);
            ulonglong2 wv1 = *(const ulonglong2*)(wrow + 2);
            ulonglong2 wv2 = *(const ulonglong2*)(wrow + 4);
            ull wp0 = wv0.x, wp1 = wv0.y, wp2 = wv1.x, wp3 = wv1.y, wp4 = wv2.x, wp5 = wv2.y;
            float h[8] = {hA.x, hA.y, hA.z, hA.w, hB.x, hB.y, hB.z, hB.w};
#pragma unroll
            for (int i = 0; i < 8; i++) {
                ull hb = pack2(h[i], h[i]);
                a2[0][i] = fma2(wp0, hb, a2[0][i]);
                a2[1][i] = fma2(wp1, hb, a2[1][i]);
                a2[2][i] = fma2(wp2, hb, a2[2][i]);
                a2[3][i] = fma2(wp3, hb, a2[3][i]);
                a2[4][i] = fma2(wp4, hb, a2[4][i]);
                a2[5][i] = fma2(wp5, hb, a2[5][i]);
            }
        }

        // ---- epilogue: silu * cutoff, staged through sOut (= sH1) ----
        float* sOut = sH1;                  // [e<128][64]
        for (int cc = 0; cc < 3; cc++) {
            __syncthreads();                // first pass also fences phase-0 sH1 readers
#pragma unroll
            for (int jj = 0; jj < 6; jj++) {
                int j = 6 * c0 + jj;
                if ((j >> 5) != cc) continue;
                int p = j & 31;
#pragma unroll
                for (int i = 0; i < 8; i++) {
                    float x, y; unpack2(a2[jj][i], x, y);
                    float Cv = sC[8 * r0 + i];
                    float2 v = make_float2(siluf(x) * Cv, siluf(y) * Cv);
                    *(float2*)&sOut[(8 * r0 + i) * 64 + 2 * p] = v;
                }
            }
            __syncthreads();
#pragma unroll
            for (int q = 0; q < 8; q++) {
                int lin = t + q * 256;      // 2048 float4
                int e = lin >> 4, x4 = lin & 15;
                ((float4*)(g_rfv + (E0 + e) * 192 + cc * 64))[x4] = ((const float4*)sOut)[lin];
            }
        }
        __syncthreads();                    // protect smem for next tile
    }
}

// ============== K3: dst-centric segment reduction (warp per atom) ==============
__global__ void k_reduce(const int* __restrict__ pr) {
    int lane = threadIdx.x & 31;
    int wid = threadIdx.x >> 5;
    for (int n = blockIdx.x * (blockDim.x >> 5) + wid; n < N_ATOMS;
         n += gridDim.x * (blockDim.x >> 5)) {
        float2 acc[9];
#pragma unroll
        for (int c = 0; c < 9; c++) acc[c] = make_float2(0.f, 0.f);
        int beg = g_off[n], end = g_off[n + 1];
        for (int j = beg; j < end; j++) {
            int e = g_slot[j];
            int s = pr[N_EDGES + e];                // src = row 1
            const float2* rp = (const float2*)(g_rfv + (size_t)e * 192);
            float2 r0 = rp[lane];
            float2 r1 = rp[32 + lane];
            float2 r2 = rp[64 + lane];
            const float2* cp = (const float2*)(g_comps + s * 576);
#pragma unroll
            for (int c = 0; c < 9; c++) {
                float2 v = cp[c * 32 + lane];
                float2 sc = (c == 0) ? r0 : (c < 4) ? r1 : r2;
                acc[c].x += sc.x * v.x;
                acc[c].y += sc.y * v.y;
            }
        }
        float2* mp = (float2*)(g_msg + n * 576);
#pragma unroll
        for (int c = 0; c < 9; c++) mp[c * 32 + lane] = acc[c];
    }
}

// ============== K_prod: q*(MY+YM), decompose, normalize -> g_cfn ==============
__global__ void __launch_bounds__(256) k_prod(const float* __restrict__ chg) {
    extern __shared__ float sT[];        // 576*33
    int t = threadIdx.x;
    int n0 = blockIdx.x * 32;
#pragma unroll 1
    for (int p = 0; p < 8; p++) {
        int a = p * 4 + (t >> 6);
        int g = t & 63;
        int n = n0 + a;
        float q = 1.0f + 0.1f * chg[n];
        float cm[9], cy[9];
#pragma unroll
        for (int c = 0; c < 9; c++) {
            cm[c] = g_msg[n * 576 + c * 64 + g];
            cy[c] = g_comps[n * 576 + c * 64 + g];
        }
        float M[9], Y[9];
        recon(cm, M); recon(cy, Y);
        float P[9];
#pragma unroll
        for (int j = 0; j < 9; j++) P[j] = 0.f;
        madd3(M, Y, P);
        madd3(Y, M, P);
        float tn2 = 0.f;
#pragma unroll
        for (int j = 0; j < 9; j++) { P[j] *= q; tn2 += P[j] * P[j]; }
        float invn = 1.f / (tn2 + 1.f);
        float c9[9]; decomp(P, c9);
#pragma unroll
        for (int c = 0; c < 9; c++) sT[(c * 64 + g) * 33 + a] = c9[c] * invn;
    }
    __syncthreads();
    for (int i = t; i < 18432; i += 256) {
        int a = i & 31, cf = i >> 5;
        g_cfn[cf * 20000 + n0 + a] = sT[cf * 33 + a];
    }
}

// ============== K_finish: X update ==============
__global__ void __launch_bounds__(256) k_finish(const float* __restrict__ X,
                                                const float* __restrict__ chg,
                                                float* __restrict__ out) {
    int idx = blockIdx.x * 256 + threadIdx.x;
    if (idx >= N_ATOMS * 64) return;
    int n = idx >> 6, g = idx & 63;
    float q = 1.0f + 0.1f * chg[n];
    const float* x = X + n * 576 + g * 9;
    float xv[9]; float tn = 0.f;
#pragma unroll
    for (int j = 0; j < 9; j++) { xv[j] = x[j]; tn += xv[j] * xv[j]; }
    float inv = 1.f / (tn + 1.f);
#pragma unroll
    for (int j = 0; j < 9; j++) xv[j] *= inv;
    float cd[9];
#pragma unroll
    for (int c = 0; c < 9; c++) cd[c] = g_msg[n * 576 + c * 64 + g];   // dX
    float dx[9]; recon(cd, dx);
    float dd[9];
#pragma unroll
    for (int j = 0; j < 9; j++) dd[j] = 0.f;
    madd3(dx, dx, dd);
#pragma unroll
    for (int j = 0; j < 9; j++)
        out[n * 576 + g * 9 + j] = xv[j] + dx[j] + q * dd[j];
}

// ---------------- launch ----------------
extern "C" void kernel_launch(void* const* d_in, const int* in_sizes, int n_in,
                              void* d_out, int out_size) {
    const float* X   = (const float*)d_in[0];
    const int*   pr  = (const int*)d_in[1];
    const float* dij = (const float*)d_in[2];
    const float* rf  = (const float*)d_in[3];
    const float* chg = (const float*)d_in[4];
    const float* W0  = (const float*)d_in[5];
    const float* b0  = (const float*)d_in[6];
    const float* W1  = (const float*)d_in[7];
    const float* b1  = (const float*)d_in[8];
    const float* W2  = (const float*)d_in[9];
    const float* b2  = (const float*)d_in[10];
    const float* Wt  = (const float*)d_in[11];
    float* out = (float*)d_out;

    const int smem_mlp = 17600 * 8 + (4224 + 2 * 64 * HS + 128) * 4;   // 225792
    const int smem_tr  = 576 * 33 * 4;                  // 76032
    const int smem_lin = 4096 * 8 + 16896 * 4;          // 100352
    cudaFuncSetAttribute(k_edge_mlp, cudaFuncAttributeMaxDynamicSharedMemorySize, smem_mlp);
    cudaFuncSetAttribute(k_decomp, cudaFuncAttributeMaxDynamicSharedMemorySize, smem_tr);
    cudaFuncSetAttribute(k_prod,   cudaFuncAttributeMaxDynamicSharedMemorySize, smem_tr);
    cudaFuncSetAttribute(k_lin,    cudaFuncAttributeMaxDynamicSharedMemorySize, smem_lin);

    k_zero<<<(N_ATOMS + 255) / 256, 256>>>();
    k_hist<<<(N_EDGES + 255) / 256, 256>>>(pr);
    k_scan<<<1, 1024>>>();
    k_edge_mlp<<<148, 256, smem_mlp>>>(rf, dij, W0, b0, W1, b1, W2, b2);   // slot 4: profiled
    k_scatter<<<(N_EDGES + 255) / 256, 256>>>(pr);
    k_decomp<<<625, 256, smem_tr>>>(X);
    k_lin<<<9 * LT2, 256, smem_lin>>>(Wt, 0);
    k_reduce<<<2500, 256>>>(pr);
    k_prod<<<625, 256, smem_tr>>>(chg);
    k_lin<<<9 * LT2, 256, smem_lin>>>(Wt, 1);
    k_finish<<<(N_ATOMS * 64 + 255) / 256, 256>>>(X, chg, out);
}

// round 17
// speedup vs baseline: 1.6730x; 1.0243x over previous
#include <cuda_runtime.h>
#include <math.h>

#define N_ATOMS 20000
#define N_EDGES 320000
#define FDIM    64
#define NTILES  2500     // N_EDGES / 128
#define LT2     79       // ceil(20000/256) row-tiles for k_lin

typedef unsigned long long ull;

// ---------------- device scratch (static, no allocations) ----------------
__device__ float g_comps[N_ATOMS * 9 * FDIM];   // Y (lin-pre out), [n][c][g]
__device__ float g_msg  [N_ATOMS * 9 * FDIM];   // messages [n][c][g]; later dX
__device__ float g_cfn  [9 * FDIM * N_ATOMS];   // comps in [c][f][n]
__device__ float g_rfv  [N_EDGES * 192];        // edge radial feats [e][k][f]
__device__ int   g_cnt [N_ATOMS];
__device__ int   g_off [N_ATOMS + 1];
__device__ int   g_cur [N_ATOMS];
__device__ int   g_slot[N_EDGES];

// ---------------- helpers ----------------
__device__ __forceinline__ ull pack2(float x, float y) {
    ull r; asm("mov.b64 %0, {%1,%2};" : "=l"(r) : "f"(x), "f"(y)); return r;
}
__device__ __forceinline__ void unpack2(ull v, float& x, float& y) {
    asm("mov.b64 {%0,%1}, %2;" : "=f"(x), "=f"(y) : "l"(v));
}
__device__ __forceinline__ ull fma2(ull a, ull b, ull c) {
    ull d; asm("fma.rn.f32x2 %0, %1, %2, %3;" : "=l"(d) : "l"(a), "l"(b), "l"(c)); return d;
}
__device__ __forceinline__ float siluf(float x) {
    return __fdividef(x, 1.0f + __expf(-x));
}
// comps order: 0:i  1:a01 2:a02 3:a12  4:s00 5:s01 6:s02 7:s11 8:s12
__device__ __forceinline__ void recon(const float* c, float* T) {
    T[0] = c[0] + c[4];  T[1] = c[1] + c[5];  T[2] = c[2] + c[6];
    T[3] = c[5] - c[1];  T[4] = c[0] + c[7];  T[5] = c[3] + c[8];
    T[6] = c[6] - c[2];  T[7] = c[8] - c[3];  T[8] = c[0] - c[4] - c[7];
}
__device__ __forceinline__ void madd3(const float* A, const float* B, float* P) {
#pragma unroll
    for (int i = 0; i < 3; i++)
#pragma unroll
        for (int j = 0; j < 3; j++) {
            float s = P[i * 3 + j];
#pragma unroll
            for (int k = 0; k < 3; k++) s += A[i * 3 + k] * B[k * 3 + j];
            P[i * 3 + j] = s;
        }
}
__device__ __forceinline__ void decomp(const float* P, float* c) {
    float dm = (P[0] + P[4] + P[8]) * (1.0f / 3.0f);
    c[0] = dm;
    c[1] = 0.5f * (P[1] - P[3]);
    c[2] = 0.5f * (P[2] - P[6]);
    c[3] = 0.5f * (P[5] - P[7]);
    c[4] = P[0] - dm;
    c[5] = 0.5f * (P[1] + P[3]);
    c[6] = 0.5f * (P[2] + P[6]);
    c[7] = P[4] - dm;
    c[8] = 0.5f * (P[5] + P[7]);
}

// ============== K_decomp: normalize X, decompose -> g_cfn [c][f][n] ==============
__global__ void __launch_bounds__(256) k_decomp(const float* __restrict__ X) {
    extern __shared__ float sT[];        // 576*33 = 19008 floats
    int t = threadIdx.x;
    int n0 = blockIdx.x * 32;
#pragma unroll 1
    for (int p = 0; p < 8; p++) {
        int a = p * 4 + (t >> 6);        // 0..31
        int f = t & 63;
        int n = n0 + a;
        const float* x = X + n * 576 + f * 9;
        float xv[9]; float tn = 0.f;
#pragma unroll
        for (int j = 0; j < 9; j++) { xv[j] = x[j]; tn += xv[j] * xv[j]; }
        float inv = 1.f / (tn + 1.f);
#pragma unroll
        for (int j = 0; j < 9; j++) xv[j] *= inv;
        float c9[9]; decomp(xv, c9);
#pragma unroll
        for (int c = 0; c < 9; c++) sT[(c * 64 + f) * 33 + a] = c9[c];
    }
    __syncthreads();
    for (int i = t; i < 18432; i += 256) {
        int a = i & 31, cf = i >> 5;
        g_cfn[cf * 20000 + n0 + a] = sT[cf * 33 + a];
    }
}

// ============== K_lin: per-c GEMM, 256-row tiles, (w,w)-dup weights ==============
__global__ void __launch_bounds__(256) k_lin(const float* __restrict__ Wt, int post) {
    extern __shared__ ull sml[];
    ull*   sW = sml;                     // 4096 : [k<64][g<64] (w,w)
    float* sA = (float*)(sml + 4096);    // 64*264 = 16896 floats
    int t = threadIdx.x;
    int c  = blockIdx.x / LT2;
    int tb = blockIdx.x % LT2;
    int m = (c == 0) ? 0 : (c < 4) ? 1 : 2;
    const float* W = Wt + (post ? 3 : 0) * 4096 + m * 4096;
    for (int i = t; i < 4096; i += 256) {
        int k = i >> 6, g = i & 63;
        float w = W[g * 64 + k];
        sW[i] = pack2(w, w);
    }
    int n0 = tb * 256;
    int rows = N_ATOMS - n0; if (rows > 256) rows = 256;
    for (int i = t; i < 16384; i += 256) {
        int f = i >> 8, nl = i & 255;
        sA[f * 264 + nl] = (nl < rows) ? g_cfn[(c * 64 + f) * 20000 + n0 + nl] : 0.f;
    }
    __syncthreads();
    int r0 = t >> 4;
    int c0 = t & 15;
    ull acc[4][8];
#pragma unroll
    for (int j = 0; j < 4; j++)
#pragma unroll
        for (int p = 0; p < 8; p++) acc[j][p] = 0;
#pragma unroll 2
    for (int k = 0; k < 64; k++) {
        const float* row = sA + k * 264;
        ulonglong2 hA = *(const ulonglong2*)&row[8 * r0];
        ulonglong2 hB = *(const ulonglong2*)&row[8 * r0 + 4];
        ulonglong2 hC = *(const ulonglong2*)&row[128 + 8 * r0];
        ulonglong2 hD = *(const ulonglong2*)&row[128 + 8 * r0 + 4];
        ulonglong2 wA = *(const ulonglong2*)(sW + k * 64 + 4 * c0);
        ulonglong2 wB = *(const ulonglong2*)(sW + k * 64 + 4 * c0 + 2);
        ull w0 = wA.x, w1 = wA.y, w2 = wB.x, w3 = wB.y;
        ull h[8] = {hA.x, hA.y, hB.x, hB.y, hC.x, hC.y, hD.x, hD.y};
#pragma unroll
        for (int p = 0; p < 8; p++) {
            acc[0][p] = fma2(w0, h[p], acc[0][p]);
            acc[1][p] = fma2(w1, h[p], acc[1][p]);
            acc[2][p] = fma2(w2, h[p], acc[2][p]);
            acc[3][p] = fma2(w3, h[p], acc[3][p]);
        }
    }
    __syncthreads();
    float* sO = sA;                      // [nl<256][66]
#pragma unroll
    for (int j = 0; j < 4; j++) {
        int g = 4 * c0 + j;
#pragma unroll
        for (int p = 0; p < 8; p++) {
            int rb = (p < 4) ? (8 * r0 + 2 * p) : (128 + 8 * r0 + 2 * (p - 4));
            float x, y; unpack2(acc[j][p], x, y);
            sO[rb * 66 + g]       = x;
            sO[(rb + 1) * 66 + g] = y;
        }
    }
    __syncthreads();
    float* outp = post ? g_msg : g_comps;
    for (int i = t; i < 16384; i += 256) {
        int nl = i >> 6, g = i & 63;
        if (nl < rows) outp[(n0 + nl) * 576 + c * 64 + g] = sO[nl * 66 + g];
    }
}

// ============== CSR build ==============
__global__ void k_zero() {
    int i = blockIdx.x * blockDim.x + threadIdx.x;
    if (i < N_ATOMS) g_cnt[i] = 0;
}
__global__ void k_hist(const int* __restrict__ pr) {
    int e = blockIdx.x * blockDim.x + threadIdx.x;
    if (e < N_EDGES) atomicAdd(&g_cnt[pr[e]], 1);   // dst = row 0
}
__global__ void k_scan() {                          // 1 block, 1024 threads
    __shared__ int s[1024];
    const int CH = 20;
    int t = threadIdx.x;
    int base = t * CH;
    int local[CH];
    int sum = 0;
#pragma unroll
    for (int i = 0; i < CH; i++) {
        int idx = base + i;
        int v = (idx < N_ATOMS) ? g_cnt[idx] : 0;
        local[i] = sum; sum += v;
    }
    s[t] = sum; __syncthreads();
    for (int d = 1; d < 1024; d <<= 1) {
        int v = (t >= d) ? s[t - d] : 0;
        __syncthreads();
        s[t] += v;
        __syncthreads();
    }
    int pre = (t == 0) ? 0 : s[t - 1];
#pragma unroll
    for (int i = 0; i < CH; i++) {
        int idx = base + i;
        if (idx < N_ATOMS) { int o = pre + local[i]; g_off[idx] = o; g_cur[idx] = o; }
    }
    if (t == 1023) g_off[N_ATOMS] = s[1023];
}
__global__ void k_scatter(const int* __restrict__ pr) {
    int e = blockIdx.x * blockDim.x + threadIdx.x;
    if (e < N_EDGES) {
        int pos = atomicAdd(&g_cur[pr[e]], 1);
        g_slot[pos] = e;
    }
}

// ============== K2: edge MLP — 512 threads, 8-edge x (1/2/3)-pair tiles ==============
#define HS 132
__global__ void __launch_bounds__(512)
k_edge_mlp(const float* __restrict__ rf, const float* __restrict__ dij,
           const float* __restrict__ W0, const float* __restrict__ b0,
           const float* __restrict__ W1, const float* __restrict__ b1,
           const float* __restrict__ W2, const float* __restrict__ b2) {
    extern __shared__ ull smu[];
    ull* sW0 = smu;                  // 1024  : [k<32][p<32]
    ull* sW1 = sW0 + 1024;           // 4096  : [k<64][p<64]
    ull* sW2 = sW1 + 4096;           // 12288 : [k<128][j<96], j = c*32+p
    ull* sB0 = sW2 + 12288;          // 32
    ull* sB1 = sB0 + 32;             // 64
    ull* sB2 = sB1 + 64;             // 96
    float* sRF = (float*)(sB2 + 96); // 4224  : [e<128][33]
    float* sH0 = sRF + 4224;         // 64*HS = 8448
    float* sH1 = sH0 + 64 * HS;      // 8448
    float* sC  = sH1 + 64 * HS;      // 128
    int t = threadIdx.x;

    for (int i = t; i < 1024; i += 512) {
        int k = i >> 5, p = i & 31;
        sW0[i] = pack2(W0[(2 * p) * 32 + k], W0[(2 * p + 1) * 32 + k]);
    }
    for (int i = t; i < 4096; i += 512) {
        int k = i >> 6, p = i & 63;
        sW1[i] = pack2(W1[(2 * p) * 64 + k], W1[(2 * p + 1) * 64 + k]);
    }
    for (int i = t; i < 12288; i += 512) {
        int k = i / 96, j = i % 96, c = j >> 5, p = j & 31;
        // output neuron o = 3f + c ; pair p covers f=2p, 2p+1
        sW2[i] = pack2(W2[(6 * p + c) * 128 + k], W2[(6 * p + 3 + c) * 128 + k]);
    }
    if (t < 32) sB0[t] = pack2(b0[2 * t], b0[2 * t + 1]);
    else if (t >= 64 && t < 128) { int u = t - 64; sB1[u] = pack2(b1[2 * u], b1[2 * u + 1]); }
    else if (t >= 128 && t < 224) {
        int u = t - 128; int c = u >> 5, p = u & 31;
        sB2[u] = pack2(b2[6 * p + c], b2[6 * p + 3 + c]);
    }
    __syncthreads();

    int r0 = t >> 5;     // 0..15 : edges 8*r0..8*r0+7
    int c0 = t & 31;     // 0..31

    for (int tile = blockIdx.x; tile < NTILES; tile += gridDim.x) {
        int E0 = tile * 128;
#pragma unroll
        for (int q = 0; q < 2; q++) {
            int lin = t + q * 512;
            float4 v = ((const float4*)(rf + E0 * 32))[lin];
            int e = lin >> 3, kq = lin & 7;
            sRF[e * 33 + 4 * kq + 0] = v.x;
            sRF[e * 33 + 4 * kq + 1] = v.y;
            sRF[e * 33 + 4 * kq + 2] = v.z;
            sRF[e * 33 + 4 * kq + 3] = v.w;
        }
        if (t < 128) {
            float d = dij[E0 + t];
            sC[t] = (d < 1.0f) ? (0.5f * (cospif(d) + 1.0f)) : 0.0f;
        }
        __syncthreads();

        // ---- L0: 32 -> 64 (pair c0; 8 edges) ----
        {
            ull a0[8];
#pragma unroll
            for (int i = 0; i < 8; i++) a0[i] = sB0[c0];
#pragma unroll 4
            for (int k = 0; k < 32; k++) {
                ull w0v = sW0[k * 32 + c0];
#pragma unroll
                for (int i = 0; i < 8; i++) {
                    float h = sRF[(8 * r0 + i) * 33 + k];
                    a0[i] = fma2(w0v, pack2(h, h), a0[i]);
                }
            }
            float lo[8], hi[8];
#pragma unroll
            for (int i = 0; i < 8; i++) {
                float x, y; unpack2(a0[i], x, y);
                lo[i] = siluf(x); hi[i] = siluf(y);
            }
            int kn = 2 * c0;
            *(float4*)&sH0[kn * HS + 8 * r0]           = make_float4(lo[0], lo[1], lo[2], lo[3]);
            *(float4*)&sH0[kn * HS + 8 * r0 + 4]       = make_float4(lo[4], lo[5], lo[6], lo[7]);
            *(float4*)&sH0[(kn + 1) * HS + 8 * r0]     = make_float4(hi[0], hi[1], hi[2], hi[3]);
            *(float4*)&sH0[(kn + 1) * HS + 8 * r0 + 4] = make_float4(hi[4], hi[5], hi[6], hi[7]);
        }
        __syncthreads();

        // ---- L1: 64 -> 128 (pairs 2*c0, 2*c0+1; 8 edges) ----
        {
            ull a1[2][8];
#pragma unroll
            for (int j = 0; j < 2; j++)
#pragma unroll
                for (int i = 0; i < 8; i++) a1[j][i] = sB1[2 * c0 + j];
#pragma unroll 2
            for (int k = 0; k < 64; k++) {
                float4 hA = *(const float4*)&sH0[k * HS + 8 * r0];
                float4 hB = *(const float4*)&sH0[k * HS + 8 * r0 + 4];
                ulonglong2 wv = *(const ulonglong2*)(sW1 + k * 64 + 2 * c0);
                ull w0v = wv.x, w1v = wv.y;
                float h[8] = {hA.x, hA.y, hA.z, hA.w, hB.x, hB.y, hB.z, hB.w};
#pragma unroll
                for (int i = 0; i < 8; i++) {
                    ull hb = pack2(h[i], h[i]);
                    a1[0][i] = fma2(w0v, hb, a1[0][i]);
                    a1[1][i] = fma2(w1v, hb, a1[1][i]);
                }
            }
            __syncthreads();   // all L1 reads of sH0 done before overwrite
#pragma unroll
            for (int j = 0; j < 2; j++) {
                int p = 2 * c0 + j;          // 0..63
                float lo[8], hi[8];
#pragma unroll
                for (int i = 0; i < 8; i++) {
                    float x, y; unpack2(a1[j][i], x, y);
                    lo[i] = siluf(x); hi[i] = siluf(y);
                }
                float* dst = (p < 32) ? sH1 : sH0;
                int kn = (p < 32) ? (2 * p) : (2 * p - 64);
                *(float4*)&dst[kn * HS + 8 * r0]           = make_float4(lo[0], lo[1], lo[2], lo[3]);
                *(float4*)&dst[kn * HS + 8 * r0 + 4]       = make_float4(lo[4], lo[5], lo[6], lo[7]);
                *(float4*)&dst[(kn + 1) * HS + 8 * r0]     = make_float4(hi[0], hi[1], hi[2], hi[3]);
                *(float4*)&dst[(kn + 1) * HS + 8 * r0 + 4] = make_float4(hi[4], hi[5], hi[6], hi[7]);
            }
        }
        __syncthreads();

        // ---- L2: 128 -> 192 (pairs 3*c0..3*c0+2; 8 edges) ----
        ull a2[3][8];
#pragma unroll
        for (int jj = 0; jj < 3; jj++)
#pragma unroll
            for (int i = 0; i < 8; i++) a2[jj][i] = sB2[3 * c0 + jj];
        // phase 0: k 0..63 from sH1
#pragma unroll 2
        for (int kl = 0; kl < 64; kl++) {
            float4 hA = *(const float4*)&sH1[kl * HS + 8 * r0];
            float4 hB = *(const float4*)&sH1[kl * HS + 8 * r0 + 4];
            const ull* wrow = sW2 + kl * 96 + 3 * c0;
            ull wp0 = wrow[0], wp1 = wrow[1], wp2 = wrow[2];
            float h[8] = {hA.x, hA.y, hA.z, hA.w, hB.x, hB.y, hB.z, hB.w};
#pragma unroll
            for (int i = 0; i < 8; i++) {
                ull hb = pack2(h[i], h[i]);
                a2[0][i] = fma2(wp0, hb, a2[0][i]);
                a2[1][i] = fma2(wp1, hb, a2[1][i]);
                a2[2][i] = fma2(wp2, hb, a2[2][i]);
            }
        }
        // phase 1: k 64..127 from sH0
#pragma unroll 2
        for (int kl = 0; kl < 64; kl++) {
            float4 hA = *(const float4*)&sH0[kl * HS + 8 * r0];
            float4 hB = *(const float4*)&sH0[kl * HS + 8 * r0 + 4];
            const ull* wrow = sW2 + (64 + kl) * 96 + 3 * c0;
            ull wp0 = wrow[0], wp1 = wrow[1], wp2 = wrow[2];
            float h[8] = {hA.x, hA.y, hA.z, hA.w, hB.x, hB.y, hB.z, hB.w};
#pragma unroll
            for (int i = 0; i < 8; i++) {
                ull hb = pack2(h[i], h[i]);
                a2[0][i] = fma2(wp0, hb, a2[0][i]);
                a2[1][i] = fma2(wp1, hb, a2[1][i]);
                a2[2][i] = fma2(wp2, hb, a2[2][i]);
            }
        }

        // ---- epilogue: silu * cutoff, staged through sOut (= sH1) ----
        float* sOut = sH1;                  // [e<128][64]
        for (int cc = 0; cc < 3; cc++) {
            __syncthreads();                // first pass also fences phase-0 sH1 readers
#pragma unroll
            for (int jj = 0; jj < 3; jj++) {
                int j = 3 * c0 + jj;
                if ((j >> 5) != cc) continue;
                int p = j & 31;
#pragma unroll
                for (int i = 0; i < 8; i++) {
                    float x, y; unpack2(a2[jj][i], x, y);
                    float Cv = sC[8 * r0 + i];
                    float2 v = make_float2(siluf(x) * Cv, siluf(y) * Cv);
                    *(float2*)&sOut[(8 * r0 + i) * 64 + 2 * p] = v;
                }
            }
            __syncthreads();
#pragma unroll
            for (int q = 0; q < 4; q++) {
                int lin = t + q * 512;      // 2048 float4
                int e = lin >> 4, x4 = lin & 15;
                ((float4*)(g_rfv + (E0 + e) * 192 + cc * 64))[x4] = ((const float4*)sOut)[lin];
            }
        }
        __syncthreads();                    // protect smem for next tile
    }
}

// ============== K3: dst-centric segment reduction (warp per atom) ==============
__global__ void k_reduce(const int* __restrict__ pr) {
    int lane = threadIdx.x & 31;
    int wid = threadIdx.x >> 5;
    for (int n = blockIdx.x * (blockDim.x >> 5) + wid; n < N_ATOMS;
         n += gridDim.x * (blockDim.x >> 5)) {
        float2 acc[9];
#pragma unroll
        for (int c = 0; c < 9; c++) acc[c] = make_float2(0.f, 0.f);
        int beg = g_off[n], end = g_off[n + 1];
        for (int j = beg; j < end; j++) {
            int e = g_slot[j];
            int s = pr[N_EDGES + e];                // src = row 1
            const float2* rp = (const float2*)(g_rfv + (size_t)e * 192);
            float2 r0 = rp[lane];
            float2 r1 = rp[32 + lane];
            float2 r2 = rp[64 + lane];
            const float2* cp = (const float2*)(g_comps + s * 576);
#pragma unroll
            for (int c = 0; c < 9; c++) {
                float2 v = cp[c * 32 + lane];
                float2 sc = (c == 0) ? r0 : (c < 4) ? r1 : r2;
                acc[c].x += sc.x * v.x;
                acc[c].y += sc.y * v.y;
            }
        }
        float2* mp = (float2*)(g_msg + n * 576);
#pragma unroll
        for (int c = 0; c < 9; c++) mp[c * 32 + lane] = acc[c];
    }
}

// ============== K_prod: q*(MY+YM), decompose, normalize -> g_cfn ==============
__global__ void __launch_bounds__(256) k_prod(const float* __restrict__ chg) {
    extern __shared__ float sT[];        // 576*33
    int t = threadIdx.x;
    int n0 = blockIdx.x * 32;
#pragma unroll 1
    for (int p = 0; p < 8; p++) {
        int a = p * 4 + (t >> 6);
        int g = t & 63;
        int n = n0 + a;
        float q = 1.0f + 0.1f * chg[n];
        float cm[9], cy[9];
#pragma unroll
        for (int c = 0; c < 9; c++) {
            cm[c] = g_msg[n * 576 + c * 64 + g];
            cy[c] = g_comps[n * 576 + c * 64 + g];
        }
        float M[9], Y[9];
        recon(cm, M); recon(cy, Y);
        float P[9];
#pragma unroll
        for (int j = 0; j < 9; j++) P[j] = 0.f;
        madd3(M, Y, P);
        madd3(Y, M, P);
        float tn2 = 0.f;
#pragma unroll
        for (int j = 0; j < 9; j++) { P[j] *= q; tn2 += P[j] * P[j]; }
        float invn = 1.f / (tn2 + 1.f);
        float c9[9]; decomp(P, c9);
#pragma unroll
        for (int c = 0; c < 9; c++) sT[(c * 64 + g) * 33 + a] = c9[c] * invn;
    }
    __syncthreads();
    for (int i = t; i < 18432; i += 256) {
        int a = i & 31, cf = i >> 5;
        g_cfn[cf * 20000 + n0 + a] = sT[cf * 33 + a];
    }
}

// ============== K_finish: X update ==============
__global__ void __launch_bounds__(256) k_finish(const float* __restrict__ X,
                                                const float* __restrict__ chg,
                                                float* __restrict__ out) {
    int idx = blockIdx.x * 256 + threadIdx.x;
    if (idx >= N_ATOMS * 64) return;
    int n = idx >> 6, g = idx & 63;
    float q = 1.0f + 0.1f * chg[n];
    const float* x = X + n * 576 + g * 9;
    float xv[9]; float tn = 0.f;
#pragma unroll
    for (int j = 0; j < 9; j++) { xv[j] = x[j]; tn += xv[j] * xv[j]; }
    float inv = 1.f / (tn + 1.f);
#pragma unroll
    for (int j = 0; j < 9; j++) xv[j] *= inv;
    float cd[9];
#pragma unroll
    for (int c = 0; c < 9; c++) cd[c] = g_msg[n * 576 + c * 64 + g];   // dX
    float dx[9]; recon(cd, dx);
    float dd[9];
#pragma unroll
    for (int j = 0; j < 9; j++) dd[j] = 0.f;
    madd3(dx, dx, dd);
#pragma unroll
    for (int j = 0; j < 9; j++)
        out[n * 576 + g * 9 + j] = xv[j] + dx[j] + q * dd[j];
}

// ---------------- launch ----------------
extern "C" void kernel_launch(void* const* d_in, const int* in_sizes, int n_in,
                              void* d_out, int out_size) {
    const float* X   = (const float*)d_in[0];
    const int*   pr  = (const int*)d_in[1];
    const float* dij = (const float*)d_in[2];
    const float* rf  = (const float*)d_in[3];
    const float* chg = (const float*)d_in[4];
    const float* W0  = (const float*)d_in[5];
    const float* b0  = (const float*)d_in[6];
    const float* W1  = (const float*)d_in[7];
    const float* b1  = (const float*)d_in[8];
    const float* W2  = (const float*)d_in[9];
    const float* b2  = (const float*)d_in[10];
    const float* Wt  = (const float*)d_in[11];
    float* out = (float*)d_out;

    const int smem_mlp = 17600 * 8 + (4224 + 2 * 64 * HS + 128) * 4;   // 225792
    const int smem_tr  = 576 * 33 * 4;                  // 76032
    const int smem_lin = 4096 * 8 + 16896 * 4;          // 100352
    cudaFuncSetAttribute(k_edge_mlp, cudaFuncAttributeMaxDynamicSharedMemorySize, smem_mlp);
    cudaFuncSetAttribute(k_decomp, cudaFuncAttributeMaxDynamicSharedMemorySize, smem_tr);
    cudaFuncSetAttribute(k_prod,   cudaFuncAttributeMaxDynamicSharedMemorySize, smem_tr);
    cudaFuncSetAttribute(k_lin,    cudaFuncAttributeMaxDynamicSharedMemorySize, smem_lin);

    k_zero<<<(N_ATOMS + 255) / 256, 256>>>();
    k_hist<<<(N_EDGES + 255) / 256, 256>>>(pr);
    k_scan<<<1, 1024>>>();
    k_edge_mlp<<<148, 512, smem_mlp>>>(rf, dij, W0, b0, W1, b1, W2, b2);   // slot 4: profiled
    k_scatter<<<(N_EDGES + 255) / 256, 256>>>(pr);
    k_decomp<<<625, 256, smem_tr>>>(X);
    k_lin<<<9 * LT2, 256, smem_lin>>>(Wt, 0);
    k_reduce<<<2500, 256>>>(pr);
    k_prod<<<625, 256, smem_tr>>>(chg);
    k_lin<<<9 * LT2, 256, smem_lin>>>(Wt, 1);
    k_finish<<<(N_ATOMS * 64 + 255) / 256, 256>>>(X, chg, out);
}